// round 16
// baseline (speedup 1.0000x reference)
#include <cuda_runtime.h>
#include <math.h>

#define N_NODES 512
#define TDIM 288
#define LDIM 128
#define BBATCH 4
#define MROWS (BBATCH * N_NODES)   // 2048

typedef unsigned long long u64;
typedef unsigned int u32;

// ---- packed f32x2 helpers (sm_100+) ----
__device__ __forceinline__ u64 add2(u64 a, u64 b) {
    u64 r; asm("add.rn.f32x2 %0,%1,%2;" : "=l"(r) : "l"(a), "l"(b)); return r;
}
__device__ __forceinline__ u64 fma2(u64 a, u64 b, u64 c) {
    u64 r; asm("fma.rn.f32x2 %0,%1,%2,%3;" : "=l"(r) : "l"(a), "l"(b), "l"(c)); return r;
}
__device__ __forceinline__ float lo32(u64 v) { return __uint_as_float((unsigned)(v & 0xffffffffu)); }
__device__ __forceinline__ float hi32(u64 v) { return __uint_as_float((unsigned)(v >> 32)); }
__device__ __forceinline__ u64 pack2(float x, float y) {
    return ((u64)__float_as_uint(y) << 32) | (u64)__float_as_uint(x);
}

// ---- tf32 helpers ----
__device__ __forceinline__ u32 tf32_bits(float v) {
    u32 r; asm("cvt.rna.tf32.f32 %0,%1;" : "=r"(r) : "f"(v));
    return r;
}
__device__ __forceinline__ void mma_tf32(float* d, const u32* a, const u32* b) {
    asm("mma.sync.aligned.m16n8k8.row.col.f32.tf32.tf32.f32 "
        "{%0,%1,%2,%3}, {%4,%5,%6,%7}, {%8,%9}, {%0,%1,%2,%3};"
        : "+f"(d[0]), "+f"(d[1]), "+f"(d[2]), "+f"(d[3])
        : "r"(a[0]), "r"(a[1]), "r"(a[2]), "r"(a[3]), "r"(b[0]), "r"(b[1]));
}

// ---- cp.async helpers ----
__device__ __forceinline__ void cpa16(u32 s, const void* g) {
    asm volatile("cp.async.ca.shared.global [%0], [%1], 16;" :: "r"(s), "l"(g));
}
__device__ __forceinline__ void cp_commit() {
    asm volatile("cp.async.commit_group;");
}
template <int N> __device__ __forceinline__ void cp_wait() {
    asm volatile("cp.async.wait_group %0;" :: "n"(N));
}

// ---- MUFU-free math ----
__device__ __forceinline__ float rcp_nt(float a) {
    float y = __int_as_float(0x7EF477D5 - __float_as_int(a));
    y = y * fmaf(-a, y, 2.0f);
    y = y * fmaf(-a, y, 2.0f);
    y = y * fmaf(-a, y, 2.0f);
    return y;
}
__device__ __forceinline__ float sigmoid_fma(float z) {
    float t = z * -1.4426950408889634f;
    t = fminf(fmaxf(t, -100.f), 100.f);
    int ii = __float2int_rn(t);
    float f = t - (float)ii;
    float p = 1.5403530e-4f;
    p = fmaf(p, f, 1.3333558e-3f);
    p = fmaf(p, f, 9.6181291e-3f);
    p = fmaf(p, f, 5.5504109e-2f);
    p = fmaf(p, f, 2.4022651e-1f);
    p = fmaf(p, f, 6.9314718e-1f);
    p = fmaf(p, f, 1.0f);
    float e = p * __int_as_float((ii + 127) << 23);
    return rcp_nt(1.0f + e);
}

// Scratch (device globals)
__device__ float g_X1[MROWS * LDIM];
__device__ float g_X2[MROWS * LDIM];
__device__ float g_S1[MROWS * LDIM];
__device__ float g_S2P[MROWS * LDIM];
__device__ float g_P[BBATCH * N_NODES * N_NODES];   // partial LOGITS (atomic)

// ---------------------------------------------------------------------------
// Zero-init for g_P (needed every launch: pairwise accumulates atomically).
// ---------------------------------------------------------------------------
__global__ __launch_bounds__(256)
void init_P()
{
    int i = blockIdx.x * 256 + threadIdx.x;     // 262144 float4
    ((float4*)g_P)[i] = make_float4(0.f, 0.f, 0.f, 0.f);
}

// ---------------------------------------------------------------------------
// GEMM core (R14 — frozen): BM=32, BN=64, BK=32, 8 warps, 4-stage cp.async
// ring, tf32 split in registers, 3 independent accumulator sets.
// ---------------------------------------------------------------------------
#define SROW 36
#define ST_A (32 * SROW)
#define ST_B (64 * SROW)
#define ST_SZ (ST_A + ST_B)
#define NSTAGE 4
#define GEMM_SMEM_FLOATS (NSTAGE * ST_SZ)   // 55296 B

__device__ __forceinline__ void split1(float v, u32& h, u32& l) {
    h = tf32_bits(v);
    l = tf32_bits(v - __uint_as_float(h));
}

struct Acc3 {
    float hh[2][4], hl[2][4], lh[2][4];
    __device__ __forceinline__ void zero() {
#pragma unroll
        for (int nf = 0; nf < 2; nf++)
#pragma unroll
            for (int e = 0; e < 4; e++) {
                hh[nf][e] = 0.f; hl[nf][e] = 0.f; lh[nf][e] = 0.f;
            }
    }
    __device__ __forceinline__ float get(int nf, int e) const {
        return hh[nf][e] + (hl[nf][e] + lh[nf][e]);
    }
};

__device__ __forceinline__ void mma_chunk_cvt(Acc3& A3,
                                              const float* SA, const float* SB,
                                              int wm, int wn, int gid, int ctid) {
    const int ar0 = (wm * 16 + gid) * SROW;
    const int ar1 = (wm * 16 + gid + 8) * SROW;
#pragma unroll
    for (int kk = 0; kk < 4; kk++) {
        int k8 = kk * 8;
        float av[4], bv[2][2];
        av[0] = SA[ar0 + k8 + ctid];
        av[1] = SA[ar1 + k8 + ctid];
        av[2] = SA[ar0 + k8 + ctid + 4];
        av[3] = SA[ar1 + k8 + ctid + 4];
#pragma unroll
        for (int nf = 0; nf < 2; nf++) {
            int r = (wn * 16 + nf * 8 + gid) * SROW;
            bv[nf][0] = SB[r + k8 + ctid];
            bv[nf][1] = SB[r + k8 + ctid + 4];
        }
        u32 ah[4], al[4], bh[2][2], bl[2][2];
#pragma unroll
        for (int i = 0; i < 4; i++) split1(av[i], ah[i], al[i]);
#pragma unroll
        for (int nf = 0; nf < 2; nf++) {
            split1(bv[nf][0], bh[nf][0], bl[nf][0]);
            split1(bv[nf][1], bh[nf][1], bl[nf][1]);
        }
#pragma unroll
        for (int nf = 0; nf < 2; nf++) {
            mma_tf32(A3.hh[nf], ah, bh[nf]);
            mma_tf32(A3.hl[nf], ah, bl[nf]);
            mma_tf32(A3.lh[nf], al, bh[nf]);
        }
    }
}

// Stage 1: [X1|X2] = leaky(x @ [W1;W2]^T + bias). grid (64, 4).
__global__ __launch_bounds__(256)
void stage1_mma(const float* __restrict__ x,
                const float* __restrict__ W1, const float* __restrict__ W2,
                const float* __restrict__ b1, const float* __restrict__ b2,
                float* __restrict__ X1, float* __restrict__ X2)
{
    extern __shared__ __align__(16) float gsm[];
    const u32 sb = (u32)__cvta_generic_to_shared(gsm);

    const int t = threadIdx.x;
    const int lane = t & 31, warp = t >> 5;
    const int wm = warp >> 2, wn = warp & 3;
    const int gid = lane >> 2, ctid = lane & 3;
    const int m0 = blockIdx.x * 32;
    const int n0 = blockIdx.y * 64;

    const int arI = t >> 3, ak = (t & 7) * 4;
    const int brI = t >> 3, bk = (t & 7) * 4;
    const float* aG  = x + (size_t)(m0 + arI) * TDIM + ak;
    const int bn1 = n0 + brI, bn2 = n0 + brI + 32;
    const float* bG1 = (bn1 < 128) ? W1 + (size_t)bn1 * TDIM + bk
                                   : W2 + (size_t)(bn1 - 128) * TDIM + bk;
    const float* bG2 = (bn2 < 128) ? W1 + (size_t)bn2 * TDIM + bk
                                   : W2 + (size_t)(bn2 - 128) * TDIM + bk;
    const u32 sA  = sb + (arI * SROW + ak) * 4;
    const u32 sB1 = sb + (ST_A + brI * SROW + bk) * 4;
    const u32 sB2 = sb + (ST_A + (brI + 32) * SROW + bk) * 4;

    Acc3 A3; A3.zero();
    const int nt = TDIM / 32;   // 9

#define S1_ISSUE(ch) do {                                  \
        int kc_ = (ch) * 32;                               \
        u32 so_ = (u32)(((ch) & 3) * ST_SZ * 4);           \
        cpa16(sA  + so_, aG  + kc_);                       \
        cpa16(sB1 + so_, bG1 + kc_);                       \
        cpa16(sB2 + so_, bG2 + kc_);                       \
        cp_commit();                                       \
    } while (0)

    S1_ISSUE(0); S1_ISSUE(1); S1_ISSUE(2);
    for (int ti = 0; ti < nt; ti++) {
        cp_wait<2>();
        __syncthreads();
        if (ti + 3 < nt) S1_ISSUE(ti + 3);
        const float* stg = gsm + (ti & 3) * ST_SZ;
        mma_chunk_cvt(A3, stg, stg + ST_A, wm, wn, gid, ctid);
        __syncthreads();
    }
#undef S1_ISSUE

    const int half = (n0 < 128);
    float* OUT = half ? X1 : X2;
    const float* bias = half ? b1 : b2;
    const int nloc0 = half ? n0 : n0 - 128;
    const int row = m0 + wm * 16 + gid;
#pragma unroll
    for (int nf = 0; nf < 2; nf++) {
        int col = nloc0 + wn * 16 + nf * 8 + 2 * ctid;
        float v0 = A3.get(nf, 0) + bias[col];
        float v1 = A3.get(nf, 1) + bias[col + 1];
        float v2 = A3.get(nf, 2) + bias[col];
        float v3 = A3.get(nf, 3) + bias[col + 1];
        v0 = fmaxf(v0, 0.2f * v0); v1 = fmaxf(v1, 0.2f * v1);
        v2 = fmaxf(v2, 0.2f * v2); v3 = fmaxf(v3, 0.2f * v3);
        *(float2*)&OUT[(size_t)row * LDIM + col]       = make_float2(v0, v1);
        *(float2*)&OUT[(size_t)(row + 8) * LDIM + col] = make_float2(v2, v3);
    }
}

// Stage 2: z=0: S1 = X1 @ Wp_a^T ; z=1: S2P = X2 @ Wp_b^T + bp. grid (64,2,2).
__global__ __launch_bounds__(256)
void stage2_mma(const float* __restrict__ X1, const float* __restrict__ X2,
                const float* __restrict__ Wp, const float* __restrict__ bp,
                float* __restrict__ S1, float* __restrict__ S2P)
{
    extern __shared__ __align__(16) float gsm[];
    const u32 sb = (u32)__cvta_generic_to_shared(gsm);

    const int t = threadIdx.x;
    const int lane = t & 31, warp = t >> 5;
    const int wm = warp >> 2, wn = warp & 3;
    const int gid = lane >> 2, ctid = lane & 3;
    const int m0 = blockIdx.x * 32;
    const int n0 = blockIdx.y * 64;
    const int z  = blockIdx.z;

    const float* A = z ? X2 : X1;
    const int arI = t >> 3, ak = (t & 7) * 4;
    const int brI = t >> 3, bk = (t & 7) * 4;
    const float* aG  = A + (size_t)(m0 + arI) * LDIM + ak;
    const float* bG1 = Wp + (size_t)(n0 + brI) * (2 * LDIM) + z * LDIM + bk;
    const float* bG2 = Wp + (size_t)(n0 + brI + 32) * (2 * LDIM) + z * LDIM + bk;
    const u32 sA  = sb + (arI * SROW + ak) * 4;
    const u32 sB1 = sb + (ST_A + brI * SROW + bk) * 4;
    const u32 sB2 = sb + (ST_A + (brI + 32) * SROW + bk) * 4;

    Acc3 A3; A3.zero();
    const int nt = LDIM / 32;   // 4

#define S2_ISSUE(ch) do {                                  \
        int kc_ = (ch) * 32;                               \
        u32 so_ = (u32)(((ch) & 3) * ST_SZ * 4);           \
        cpa16(sA  + so_, aG  + kc_);                       \
        cpa16(sB1 + so_, bG1 + kc_);                       \
        cpa16(sB2 + so_, bG2 + kc_);                       \
        cp_commit();                                       \
    } while (0)

    S2_ISSUE(0); S2_ISSUE(1); S2_ISSUE(2);
    for (int ti = 0; ti < nt; ti++) {
        cp_wait<2>();
        __syncthreads();
        if (ti + 3 < nt) S2_ISSUE(ti + 3);
        const float* stg = gsm + (ti & 3) * ST_SZ;
        mma_chunk_cvt(A3, stg, stg + ST_A, wm, wn, gid, ctid);
        __syncthreads();
    }
#undef S2_ISSUE

    float* OUT = z ? S2P : S1;
    const int row = m0 + wm * 16 + gid;
#pragma unroll
    for (int nf = 0; nf < 2; nf++) {
        int col = n0 + wn * 16 + nf * 8 + 2 * ctid;
        float bv0 = z ? bp[col] : 0.f;
        float bv1 = z ? bp[col + 1] : 0.f;
        *(float2*)&OUT[(size_t)row * LDIM + col] =
            make_float2(A3.get(nf, 0) + bv0, A3.get(nf, 1) + bv1);
        *(float2*)&OUT[(size_t)(row + 8) * LDIM + col] =
            make_float2(A3.get(nf, 2) + bv0, A3.get(nf, 3) + bv1);
    }
}

// ---------------------------------------------------------------------------
// Pairwise (l-split): grid (8 jx, 8 iy, 8 = b*2+half), 256 threads.
// Each block: 64x64 (i,j) tile, one b, HALF of the l range (64 floats =
// 32 u64 kk). Computes partial logit (incl. partial separable terms) and
// atomicAdd's into g_P. Exactly 2 contributions per element + zero init
// -> deterministic (IEEE add is commutative).
// smem ~34.8KB static -> 4 blocks/SM, 32 warps/SM.
// ---------------------------------------------------------------------------
#define HR2 33   // u64 per row (32 + 1 pad)

__global__ __launch_bounds__(256)
void pairwise_half_kernel(const float* __restrict__ S1, const float* __restrict__ S2P,
                          const float* __restrict__ Wb, float* __restrict__ P)
{
    __shared__ __align__(16) u64 s1t[64 * HR2];
    __shared__ __align__(16) u64 s2t[64 * HR2];
    __shared__ u64 c1[32], c2[32];
    __shared__ float rowA[64], rowB[64];

    const int t  = threadIdx.x;
    const int tx = t & 15;          // j micro col 0..15
    const int ty = t >> 4;          // i micro row 0..15
    const int j0 = blockIdx.x * 64;
    const int i0 = blockIdx.y * 64;
    const int b    = blockIdx.z >> 1;
    const int half = blockIdx.z & 1;
    const int l0   = half * 64;     // l offset (floats)

    if (t < 32) {
        float2 w = ((const float2*)(Wb + l0))[t];
        c1[t] = pack2(0.6f * w.x, 0.6f * w.y);
        c2[t] = pack2(0.4f * w.x, 0.4f * w.y);
    }

    const float4* S1v = (const float4*)(S1  + ((size_t)b * N_NODES + i0) * LDIM + l0);
    const float4* S2v = (const float4*)(S2P + ((size_t)b * N_NODES + j0) * LDIM + l0);
    // row stride in float4 units = LDIM/4 = 32; 16 float4 per half-row.
#pragma unroll
    for (int s = 0; s < 4; s++) {
        int f   = t + s * 256;          // 0..1023
        int row = f >> 4;               // 0..63
        int c4  = f & 15;
        float4 v = S1v[row * 32 + c4];
        float4 w = S2v[row * 32 + c4];
        float2* d = (float2*)&s1t[row * HR2 + c4 * 2];
        d[0] = make_float2(v.x, v.y);
        d[1] = make_float2(v.z, v.w);
        float2* e = (float2*)&s2t[row * HR2 + c4 * 2];
        e[0] = make_float2(w.x, w.y);
        e[1] = make_float2(w.z, w.w);
    }
    __syncthreads();

    // partial separable parts: t<128 -> s1 rows (2 thr/row), t>=128 -> s2 rows
    {
        int tt   = t & 127;
        int row  = tt >> 1;
        int hh   = tt & 1;
        const u64* cc  = c1 + hh * 16;
        const u64* src = ((t < 128) ? s1t : s2t) + row * HR2 + hh * 16;
        u64 a0 = 0, a1 = 0;
#pragma unroll
        for (int q = 0; q < 16; q += 2) {
            a0 = fma2(cc[q],     src[q],     a0);
            a1 = fma2(cc[q + 1], src[q + 1], a1);
        }
        float s = lo32(a0) + hi32(a0) + lo32(a1) + hi32(a1);
        s += __shfl_xor_sync(0xffffffffu, s, 1);
        if (hh == 0) {
            if (t < 128) rowA[row] = s; else rowB[row] = s;
        }
    }
    __syncthreads();

    u64 acc[4][4] = {};
    const u64 MASK = 0x7fffffff7fffffffULL;
#pragma unroll 4
    for (int kk = 0; kk < 32; kk++) {
        u64 cw = c2[kk];
        u64 ra[4], rb[4];
#pragma unroll
        for (int r = 0; r < 4; r++) ra[r] = s1t[(ty + 16 * r) * HR2 + kk];
#pragma unroll
        for (int c = 0; c < 4; c++) rb[c] = s2t[(tx + 16 * c) * HR2 + kk];
#pragma unroll
        for (int r = 0; r < 4; r++)
#pragma unroll
            for (int c = 0; c < 4; c++) {
                u64 v = add2(ra[r], rb[c]);
                acc[r][c] = fma2(cw, v & MASK, acc[r][c]);
            }
    }

    float* Pb = P + (size_t)b * N_NODES * N_NODES;
#pragma unroll
    for (int r = 0; r < 4; r++) {
        int i = i0 + ty + 16 * r;
        float ai = rowA[ty + 16 * r];
#pragma unroll
        for (int c = 0; c < 4; c++) {
            int j = j0 + tx + 16 * c;
            float v = lo32(acc[r][c]) + hi32(acc[r][c]) + ai + rowB[tx + 16 * c];
            atomicAdd(&Pb[(size_t)i * N_NODES + j], v);
        }
    }
}

// ---------------------------------------------------------------------------
// Finalize: sigmoid(logit + bb) per plane, mean over b, diag mask,
// MUFU-free logit/noise epilogue (out = 1/(1 + R^-5)).
// ---------------------------------------------------------------------------
__global__ __launch_bounds__(128)
void finalize_kernel(const float* __restrict__ P, const float* __restrict__ noise,
                     const float* __restrict__ bb, float* __restrict__ out)
{
    int q = blockIdx.x * 128 + threadIdx.x;   // float4 index
    const int PL4 = N_NODES * N_NODES / 4;
    float4 p0 = ((const float4*)P)[q];
    float4 p1 = ((const float4*)P)[q + PL4];
    float4 p2 = ((const float4*)P)[q + 2 * PL4];
    float4 p3 = ((const float4*)P)[q + 3 * PL4];
    float4 ns = ((const float4*)noise)[q];
    const float bbv = bb[0];

    int idx0 = q * 4;
    int i = idx0 >> 9;
    int jbase = idx0 & (N_NODES - 1);

    float l0[4] = { p0.x, p0.y, p0.z, p0.w };
    float l1[4] = { p1.x, p1.y, p1.z, p1.w };
    float l2[4] = { p2.x, p2.y, p2.z, p2.w };
    float l3[4] = { p3.x, p3.y, p3.z, p3.w };
    float nv[4] = { ns.x, ns.y, ns.z, ns.w };
    float4 o;
    float* op = (float*)&o;
#pragma unroll
    for (int e = 0; e < 4; e++) {
        float p = 0.25f * (sigmoid_fma(l0[e] + bbv) + sigmoid_fma(l1[e] + bbv)
                         + sigmoid_fma(l2[e] + bbv) + sigmoid_fma(l3[e] + bbv));
        if (i == jbase + e) p = 0.f;
        float r1 = (p + 1e-10f) * rcp_nt(1.0f + (1e-10f - p));
        r1 = fminf(fmaxf(r1, 4.5399930e-5f), 22026.466f);
        float invR = (1.0f - nv[e]) * rcp_nt(r1 * nv[e]);
        float i2 = invR * invR;
        float tpw = fminf(i2 * i2 * invR, 1e30f);
        op[e] = rcp_nt(1.0f + tpw);
    }
    ((float4*)out)[q] = o;
}

// ---------------------------------------------------------------------------
extern "C" void kernel_launch(void* const* d_in, const int* in_sizes, int n_in,
                              void* d_out, int out_size)
{
    const float* x     = (const float*)d_in[0];
    const float* W1    = (const float*)d_in[1];
    const float* b1    = (const float*)d_in[2];
    const float* W2    = (const float*)d_in[3];
    const float* b2    = (const float*)d_in[4];
    const float* Wp    = (const float*)d_in[5];
    const float* bp    = (const float*)d_in[6];
    const float* Wb    = (const float*)d_in[7];
    const float* bb    = (const float*)d_in[8];
    const float* noise = (const float*)d_in[9];
    float* out = (float*)d_out;

    float *X1, *X2, *S1, *S2P, *P;
    cudaGetSymbolAddress((void**)&X1,  g_X1);
    cudaGetSymbolAddress((void**)&X2,  g_X2);
    cudaGetSymbolAddress((void**)&S1,  g_S1);
    cudaGetSymbolAddress((void**)&S2P, g_S2P);
    cudaGetSymbolAddress((void**)&P,   g_P);

    const size_t gemm_smem = (size_t)GEMM_SMEM_FLOATS * sizeof(float);  // 55296 B
    cudaFuncSetAttribute(stage1_mma, cudaFuncAttributeMaxDynamicSharedMemorySize,
                         (int)gemm_smem);
    cudaFuncSetAttribute(stage2_mma, cudaFuncAttributeMaxDynamicSharedMemorySize,
                         (int)gemm_smem);

    // Stage 0: zero the logit accumulator (1M floats)
    init_P<<<BBATCH * N_NODES * N_NODES / 4 / 256, 256>>>();

    // Stage 1: [X1|X2] = leaky(x @ [W1;W2]^T + bias)
    stage1_mma<<<dim3(MROWS / 32, 4), 256, gemm_smem>>>(x, W1, W2, b1, b2, X1, X2);

    // Stage 2: S1 = X1@Wp_a^T, S2P = X2@Wp_b^T + bp
    stage2_mma<<<dim3(MROWS / 32, 2, 2), 256, gemm_smem>>>(X1, X2, Wp, bp, S1, S2P);

    // Stage 3: pairwise partial logits (l split in half; 512 blocks)
    dim3 g3(N_NODES / 64, N_NODES / 64, BBATCH * 2);   // 8 x 8 x 8
    pairwise_half_kernel<<<g3, dim3(256)>>>(S1, S2P, Wb, P);

    // Stage 4: sigmoid + mean + epilogue
    finalize_kernel<<<N_NODES * N_NODES / 4 / 128, 128>>>(P, noise, bb, out);
}

// round 17
// speedup vs baseline: 1.0465x; 1.0465x over previous
#include <cuda_runtime.h>
#include <math.h>

#define N_NODES 512
#define TDIM 288
#define LDIM 128
#define BBATCH 4
#define MROWS (BBATCH * N_NODES)   // 2048

typedef unsigned long long u64;
typedef unsigned int u32;

// ---- packed f32x2 helpers (sm_100+) ----
__device__ __forceinline__ u64 add2(u64 a, u64 b) {
    u64 r; asm("add.rn.f32x2 %0,%1,%2;" : "=l"(r) : "l"(a), "l"(b)); return r;
}
__device__ __forceinline__ u64 fma2(u64 a, u64 b, u64 c) {
    u64 r; asm("fma.rn.f32x2 %0,%1,%2,%3;" : "=l"(r) : "l"(a), "l"(b), "l"(c)); return r;
}
__device__ __forceinline__ float lo32(u64 v) { return __uint_as_float((unsigned)(v & 0xffffffffu)); }
__device__ __forceinline__ float hi32(u64 v) { return __uint_as_float((unsigned)(v >> 32)); }
__device__ __forceinline__ u64 pack2(float x, float y) {
    return ((u64)__float_as_uint(y) << 32) | (u64)__float_as_uint(x);
}

// ---- tf32 helpers ----
__device__ __forceinline__ u32 tf32_bits(float v) {
    u32 r; asm("cvt.rna.tf32.f32 %0,%1;" : "=r"(r) : "f"(v));
    return r;
}
__device__ __forceinline__ void mma_tf32(float* d, const u32* a, const u32* b) {
    asm("mma.sync.aligned.m16n8k8.row.col.f32.tf32.tf32.f32 "
        "{%0,%1,%2,%3}, {%4,%5,%6,%7}, {%8,%9}, {%0,%1,%2,%3};"
        : "+f"(d[0]), "+f"(d[1]), "+f"(d[2]), "+f"(d[3])
        : "r"(a[0]), "r"(a[1]), "r"(a[2]), "r"(a[3]), "r"(b[0]), "r"(b[1]));
}

// ---- cp.async helpers ----
__device__ __forceinline__ void cpa16(u32 s, const void* g) {
    asm volatile("cp.async.ca.shared.global [%0], [%1], 16;" :: "r"(s), "l"(g));
}
__device__ __forceinline__ void cp_commit() {
    asm volatile("cp.async.commit_group;");
}
template <int N> __device__ __forceinline__ void cp_wait() {
    asm volatile("cp.async.wait_group %0;" :: "n"(N));
}

// ---- MUFU-free math ----
__device__ __forceinline__ float rcp_nt(float a) {
    float y = __int_as_float(0x7EF477D5 - __float_as_int(a));
    y = y * fmaf(-a, y, 2.0f);
    y = y * fmaf(-a, y, 2.0f);
    y = y * fmaf(-a, y, 2.0f);
    return y;
}
__device__ __forceinline__ float sigmoid_fma(float z) {
    float t = z * -1.4426950408889634f;
    t = fminf(fmaxf(t, -100.f), 100.f);
    int ii = __float2int_rn(t);
    float f = t - (float)ii;
    float p = 1.5403530e-4f;
    p = fmaf(p, f, 1.3333558e-3f);
    p = fmaf(p, f, 9.6181291e-3f);
    p = fmaf(p, f, 5.5504109e-2f);
    p = fmaf(p, f, 2.4022651e-1f);
    p = fmaf(p, f, 6.9314718e-1f);
    p = fmaf(p, f, 1.0f);
    float e = p * __int_as_float((ii + 127) << 23);
    return rcp_nt(1.0f + e);
}

// Scratch (device globals)
__device__ float g_X1[MROWS * LDIM];
__device__ float g_X2[MROWS * LDIM];
__device__ float g_S1[MROWS * LDIM];
__device__ float g_S2P[MROWS * LDIM];
__device__ float g_P[BBATCH * N_NODES * N_NODES];

// ---------------------------------------------------------------------------
// GEMM core (R14 — frozen): BM=32, BN=64, BK=32, 8 warps, 4-stage cp.async
// ring, tf32 split in registers, 3 independent accumulator sets.
// ---------------------------------------------------------------------------
#define SROW 36
#define ST_A (32 * SROW)
#define ST_B (64 * SROW)
#define ST_SZ (ST_A + ST_B)
#define NSTAGE 4
#define GEMM_SMEM_FLOATS (NSTAGE * ST_SZ)   // 55296 B

__device__ __forceinline__ void split1(float v, u32& h, u32& l) {
    h = tf32_bits(v);
    l = tf32_bits(v - __uint_as_float(h));
}

struct Acc3 {
    float hh[2][4], hl[2][4], lh[2][4];
    __device__ __forceinline__ void zero() {
#pragma unroll
        for (int nf = 0; nf < 2; nf++)
#pragma unroll
            for (int e = 0; e < 4; e++) {
                hh[nf][e] = 0.f; hl[nf][e] = 0.f; lh[nf][e] = 0.f;
            }
    }
    __device__ __forceinline__ float get(int nf, int e) const {
        return hh[nf][e] + (hl[nf][e] + lh[nf][e]);
    }
};

__device__ __forceinline__ void mma_chunk_cvt(Acc3& A3,
                                              const float* SA, const float* SB,
                                              int wm, int wn, int gid, int ctid) {
    const int ar0 = (wm * 16 + gid) * SROW;
    const int ar1 = (wm * 16 + gid + 8) * SROW;
#pragma unroll
    for (int kk = 0; kk < 4; kk++) {
        int k8 = kk * 8;
        float av[4], bv[2][2];
        av[0] = SA[ar0 + k8 + ctid];
        av[1] = SA[ar1 + k8 + ctid];
        av[2] = SA[ar0 + k8 + ctid + 4];
        av[3] = SA[ar1 + k8 + ctid + 4];
#pragma unroll
        for (int nf = 0; nf < 2; nf++) {
            int r = (wn * 16 + nf * 8 + gid) * SROW;
            bv[nf][0] = SB[r + k8 + ctid];
            bv[nf][1] = SB[r + k8 + ctid + 4];
        }
        u32 ah[4], al[4], bh[2][2], bl[2][2];
#pragma unroll
        for (int i = 0; i < 4; i++) split1(av[i], ah[i], al[i]);
#pragma unroll
        for (int nf = 0; nf < 2; nf++) {
            split1(bv[nf][0], bh[nf][0], bl[nf][0]);
            split1(bv[nf][1], bh[nf][1], bl[nf][1]);
        }
#pragma unroll
        for (int nf = 0; nf < 2; nf++) {
            mma_tf32(A3.hh[nf], ah, bh[nf]);
            mma_tf32(A3.hl[nf], ah, bl[nf]);
            mma_tf32(A3.lh[nf], al, bh[nf]);
        }
    }
}

// Stage 1: [X1|X2] = leaky(x @ [W1;W2]^T + bias). grid (64, 4).
__global__ __launch_bounds__(256)
void stage1_mma(const float* __restrict__ x,
                const float* __restrict__ W1, const float* __restrict__ W2,
                const float* __restrict__ b1, const float* __restrict__ b2,
                float* __restrict__ X1, float* __restrict__ X2)
{
    extern __shared__ __align__(16) float gsm[];
    const u32 sb = (u32)__cvta_generic_to_shared(gsm);

    const int t = threadIdx.x;
    const int lane = t & 31, warp = t >> 5;
    const int wm = warp >> 2, wn = warp & 3;
    const int gid = lane >> 2, ctid = lane & 3;
    const int m0 = blockIdx.x * 32;
    const int n0 = blockIdx.y * 64;

    const int arI = t >> 3, ak = (t & 7) * 4;
    const int brI = t >> 3, bk = (t & 7) * 4;
    const float* aG  = x + (size_t)(m0 + arI) * TDIM + ak;
    const int bn1 = n0 + brI, bn2 = n0 + brI + 32;
    const float* bG1 = (bn1 < 128) ? W1 + (size_t)bn1 * TDIM + bk
                                   : W2 + (size_t)(bn1 - 128) * TDIM + bk;
    const float* bG2 = (bn2 < 128) ? W1 + (size_t)bn2 * TDIM + bk
                                   : W2 + (size_t)(bn2 - 128) * TDIM + bk;
    const u32 sA  = sb + (arI * SROW + ak) * 4;
    const u32 sB1 = sb + (ST_A + brI * SROW + bk) * 4;
    const u32 sB2 = sb + (ST_A + (brI + 32) * SROW + bk) * 4;

    Acc3 A3; A3.zero();
    const int nt = TDIM / 32;   // 9

#define S1_ISSUE(ch) do {                                  \
        int kc_ = (ch) * 32;                               \
        u32 so_ = (u32)(((ch) & 3) * ST_SZ * 4);           \
        cpa16(sA  + so_, aG  + kc_);                       \
        cpa16(sB1 + so_, bG1 + kc_);                       \
        cpa16(sB2 + so_, bG2 + kc_);                       \
        cp_commit();                                       \
    } while (0)

    S1_ISSUE(0); S1_ISSUE(1); S1_ISSUE(2);
    for (int ti = 0; ti < nt; ti++) {
        cp_wait<2>();
        __syncthreads();
        if (ti + 3 < nt) S1_ISSUE(ti + 3);
        const float* stg = gsm + (ti & 3) * ST_SZ;
        mma_chunk_cvt(A3, stg, stg + ST_A, wm, wn, gid, ctid);
        __syncthreads();
    }
#undef S1_ISSUE

    const int half = (n0 < 128);
    float* OUT = half ? X1 : X2;
    const float* bias = half ? b1 : b2;
    const int nloc0 = half ? n0 : n0 - 128;
    const int row = m0 + wm * 16 + gid;
#pragma unroll
    for (int nf = 0; nf < 2; nf++) {
        int col = nloc0 + wn * 16 + nf * 8 + 2 * ctid;
        float v0 = A3.get(nf, 0) + bias[col];
        float v1 = A3.get(nf, 1) + bias[col + 1];
        float v2 = A3.get(nf, 2) + bias[col];
        float v3 = A3.get(nf, 3) + bias[col + 1];
        v0 = fmaxf(v0, 0.2f * v0); v1 = fmaxf(v1, 0.2f * v1);
        v2 = fmaxf(v2, 0.2f * v2); v3 = fmaxf(v3, 0.2f * v3);
        *(float2*)&OUT[(size_t)row * LDIM + col]       = make_float2(v0, v1);
        *(float2*)&OUT[(size_t)(row + 8) * LDIM + col] = make_float2(v2, v3);
    }
}

// Stage 2: z=0: S1 = X1 @ Wp_a^T ; z=1: S2P = X2 @ Wp_b^T + bp. grid (64,2,2).
__global__ __launch_bounds__(256)
void stage2_mma(const float* __restrict__ X1, const float* __restrict__ X2,
                const float* __restrict__ Wp, const float* __restrict__ bp,
                float* __restrict__ S1, float* __restrict__ S2P)
{
    extern __shared__ __align__(16) float gsm[];
    const u32 sb = (u32)__cvta_generic_to_shared(gsm);

    const int t = threadIdx.x;
    const int lane = t & 31, warp = t >> 5;
    const int wm = warp >> 2, wn = warp & 3;
    const int gid = lane >> 2, ctid = lane & 3;
    const int m0 = blockIdx.x * 32;
    const int n0 = blockIdx.y * 64;
    const int z  = blockIdx.z;

    const float* A = z ? X2 : X1;
    const int arI = t >> 3, ak = (t & 7) * 4;
    const int brI = t >> 3, bk = (t & 7) * 4;
    const float* aG  = A + (size_t)(m0 + arI) * LDIM + ak;
    const float* bG1 = Wp + (size_t)(n0 + brI) * (2 * LDIM) + z * LDIM + bk;
    const float* bG2 = Wp + (size_t)(n0 + brI + 32) * (2 * LDIM) + z * LDIM + bk;
    const u32 sA  = sb + (arI * SROW + ak) * 4;
    const u32 sB1 = sb + (ST_A + brI * SROW + bk) * 4;
    const u32 sB2 = sb + (ST_A + (brI + 32) * SROW + bk) * 4;

    Acc3 A3; A3.zero();
    const int nt = LDIM / 32;   // 4

#define S2_ISSUE(ch) do {                                  \
        int kc_ = (ch) * 32;                               \
        u32 so_ = (u32)(((ch) & 3) * ST_SZ * 4);           \
        cpa16(sA  + so_, aG  + kc_);                       \
        cpa16(sB1 + so_, bG1 + kc_);                       \
        cpa16(sB2 + so_, bG2 + kc_);                       \
        cp_commit();                                       \
    } while (0)

    S2_ISSUE(0); S2_ISSUE(1); S2_ISSUE(2);
    for (int ti = 0; ti < nt; ti++) {
        cp_wait<2>();
        __syncthreads();
        if (ti + 3 < nt) S2_ISSUE(ti + 3);
        const float* stg = gsm + (ti & 3) * ST_SZ;
        mma_chunk_cvt(A3, stg, stg + ST_A, wm, wn, gid, ctid);
        __syncthreads();
    }
#undef S2_ISSUE

    float* OUT = z ? S2P : S1;
    const int row = m0 + wm * 16 + gid;
#pragma unroll
    for (int nf = 0; nf < 2; nf++) {
        int col = n0 + wn * 16 + nf * 8 + 2 * ctid;
        float bv0 = z ? bp[col] : 0.f;
        float bv1 = z ? bp[col + 1] : 0.f;
        *(float2*)&OUT[(size_t)row * LDIM + col] =
            make_float2(A3.get(nf, 0) + bv0, A3.get(nf, 1) + bv1);
        *(float2*)&OUT[(size_t)(row + 8) * LDIM + col] =
            make_float2(A3.get(nf, 2) + bv0, A3.get(nf, 3) + bv1);
    }
}

// ---------------------------------------------------------------------------
// Pairwise: 64x64 tile per block (one b), grid (8, 8, 4), 256 threads,
// 4x4 u64 micro-tile. kk loop is REGISTER DOUBLE-BUFFERED (prefetch kk+1
// ra/rb/cw before kk math) so the 29cy LDS latency is hidden behind a full
// math block. launch_bounds(256,3) raises the reg cap to ~85 so ptxas
// doesn't squeeze the pipeline out (smem already limits to 3 blocks/SM).
// kk+1==64 prefetch safely reads the row pad / rowA area (unused values).
// ---------------------------------------------------------------------------
#define SR2 65   // u64 per row (64 + 1 pad)
#define PW_S2   (64 * SR2)          // 4160
#define PW_C1   (2 * 64 * SR2)      // 8320
#define PW_C2   (PW_C1 + 64)        // 8384
#define PW_ROWF ((PW_C2 + 64 + 1) * 2)  // float index of rowA (pad 1 u64 after c2)
#define PW_U64_TOTAL (PW_C2 + 64 + 1 + 64)  // 8513 u64 = 68,104 bytes

__global__ __launch_bounds__(256, 3)
void pairwise_kernel(const float* __restrict__ S1, const float* __restrict__ S2P,
                     const float* __restrict__ Wb, const float* __restrict__ bb,
                     float* __restrict__ P)
{
    extern __shared__ __align__(16) u64 sm[];
    u64*   s1t  = sm;
    u64*   s2t  = sm + PW_S2;
    u64*   c1   = sm + PW_C1;
    u64*   c2   = sm + PW_C2;          // 64 entries + 1 pad u64 after
    float* rowA = ((float*)sm) + PW_ROWF;        // [64]
    float* rowB = rowA + 64;                     // [64]

    const int t  = threadIdx.x;
    const int tx = t & 15;          // j micro col 0..15
    const int ty = t >> 4;          // i micro row 0..15
    const int j0 = blockIdx.x * 64;
    const int i0 = blockIdx.y * 64;
    const int b  = blockIdx.z;

    if (t < 64) {
        float2 w = ((const float2*)Wb)[t];
        c1[t] = pack2(0.6f * w.x, 0.6f * w.y);
        c2[t] = pack2(0.4f * w.x, 0.4f * w.y);
    }

    const float4* S1v = (const float4*)(S1  + ((size_t)b * N_NODES + i0) * LDIM);
    const float4* S2v = (const float4*)(S2P + ((size_t)b * N_NODES + j0) * LDIM);
#pragma unroll
    for (int s = 0; s < 8; s++) {
        int f   = t + s * 256;          // 0..2047
        int row = f >> 5;
        int c4  = f & 31;
        float4 v = S1v[row * 32 + c4];
        float4 w = S2v[row * 32 + c4];
        float2* d = (float2*)&s1t[row * SR2 + c4 * 2];
        d[0] = make_float2(v.x, v.y);
        d[1] = make_float2(v.z, v.w);
        float2* e = (float2*)&s2t[row * SR2 + c4 * 2];
        e[0] = make_float2(w.x, w.y);
        e[1] = make_float2(w.z, w.w);
    }
    __syncthreads();

    // separable linear parts: t<128 -> s1 rows (2 thr/row), t>=128 -> s2 rows
    {
        int tt   = t & 127;
        int row  = tt >> 1;
        int half = tt & 1;
        const u64* cc  = c1 + half * 32;
        const u64* src = ((t < 128) ? s1t : s2t) + row * SR2 + half * 32;
        u64 a0 = 0, a1 = 0;
#pragma unroll
        for (int q = 0; q < 32; q += 2) {
            a0 = fma2(cc[q],     src[q],     a0);
            a1 = fma2(cc[q + 1], src[q + 1], a1);
        }
        float s = lo32(a0) + hi32(a0) + lo32(a1) + hi32(a1);
        s += __shfl_xor_sync(0xffffffffu, s, 1);
        if (half == 0) {
            if (t < 128) rowA[row] = s; else rowB[row] = s;
        }
    }
    __syncthreads();

    u64 acc[4][4] = {};
    const u64 MASK = 0x7fffffff7fffffffULL;

    const u64* s1r = s1t + ty * SR2;     // + 16*r*SR2
    const u64* s2r = s2t + tx * SR2;     // + 16*c*SR2

    u64 raC[4], rbC[4], raN[4], rbN[4];
    u64 cwC = c2[0], cwN;
#pragma unroll
    for (int r = 0; r < 4; r++) raC[r] = s1r[16 * r * SR2];
#pragma unroll
    for (int c = 0; c < 4; c++) rbC[c] = s2r[16 * c * SR2];

#pragma unroll 8
    for (int kk = 0; kk < 64; kk++) {
        // prefetch kk+1 (kk==63 reads the row pad / c2 pad -> unused)
        cwN = c2[kk + 1];
#pragma unroll
        for (int r = 0; r < 4; r++) raN[r] = s1r[16 * r * SR2 + kk + 1];
#pragma unroll
        for (int c = 0; c < 4; c++) rbN[c] = s2r[16 * c * SR2 + kk + 1];
        // math on current
#pragma unroll
        for (int r = 0; r < 4; r++)
#pragma unroll
            for (int c = 0; c < 4; c++) {
                u64 v = add2(raC[r], rbC[c]);
                acc[r][c] = fma2(cwC, v & MASK, acc[r][c]);
            }
        cwC = cwN;
#pragma unroll
        for (int r = 0; r < 4; r++) raC[r] = raN[r];
#pragma unroll
        for (int c = 0; c < 4; c++) rbC[c] = rbN[c];
    }

    const float bbv = bb[0];
    float* Pb = P + (size_t)b * N_NODES * N_NODES;
#pragma unroll
    for (int r = 0; r < 4; r++) {
        int i = i0 + ty + 16 * r;
        float ai = rowA[ty + 16 * r] + bbv;
#pragma unroll
        for (int c = 0; c < 4; c++) {
            int j = j0 + tx + 16 * c;
            float z = lo32(acc[r][c]) + hi32(acc[r][c])
                    + ai + rowB[tx + 16 * c];
            Pb[(size_t)i * N_NODES + j] = sigmoid_fma(z);
        }
    }
}

// ---------------------------------------------------------------------------
// Finalize (MUFU-free): out = 1/(1 + R^-5). 2 float4 per thread for MLP.
// ---------------------------------------------------------------------------
__global__ __launch_bounds__(128)
void finalize_kernel(const float* __restrict__ P, const float* __restrict__ noise,
                     float* __restrict__ out)
{
    const int PL4 = N_NODES * N_NODES / 4;       // 65536
    int q0 = blockIdx.x * 128 + threadIdx.x;     // 0..32767
#pragma unroll
    for (int h = 0; h < 2; h++) {
        int q = q0 + h * 32768;
        float4 p0 = ((const float4*)P)[q];
        float4 p1 = ((const float4*)P)[q + PL4];
        float4 p2 = ((const float4*)P)[q + 2 * PL4];
        float4 p3 = ((const float4*)P)[q + 3 * PL4];
        float4 ns = ((const float4*)noise)[q];

        int idx0 = q * 4;
        int i = idx0 >> 9;
        int jbase = idx0 & (N_NODES - 1);

        float pv[4] = { 0.25f * (p0.x + p1.x + p2.x + p3.x),
                        0.25f * (p0.y + p1.y + p2.y + p3.y),
                        0.25f * (p0.z + p1.z + p2.z + p3.z),
                        0.25f * (p0.w + p1.w + p2.w + p3.w) };
        float nv[4] = { ns.x, ns.y, ns.z, ns.w };
        float4 o;
        float* op = (float*)&o;
#pragma unroll
        for (int e = 0; e < 4; e++) {
            float p = pv[e];
            if (i == jbase + e) p = 0.f;
            float r1 = (p + 1e-10f) * rcp_nt(1.0f + (1e-10f - p));
            r1 = fminf(fmaxf(r1, 4.5399930e-5f), 22026.466f);
            float invR = (1.0f - nv[e]) * rcp_nt(r1 * nv[e]);
            float i2 = invR * invR;
            float tpw = fminf(i2 * i2 * invR, 1e30f);
            op[e] = rcp_nt(1.0f + tpw);
        }
        ((float4*)out)[q] = o;
    }
}

// ---------------------------------------------------------------------------
extern "C" void kernel_launch(void* const* d_in, const int* in_sizes, int n_in,
                              void* d_out, int out_size)
{
    const float* x     = (const float*)d_in[0];
    const float* W1    = (const float*)d_in[1];
    const float* b1    = (const float*)d_in[2];
    const float* W2    = (const float*)d_in[3];
    const float* b2    = (const float*)d_in[4];
    const float* Wp    = (const float*)d_in[5];
    const float* bp    = (const float*)d_in[6];
    const float* Wb    = (const float*)d_in[7];
    const float* bb    = (const float*)d_in[8];
    const float* noise = (const float*)d_in[9];
    float* out = (float*)d_out;

    float *X1, *X2, *S1, *S2P, *P;
    cudaGetSymbolAddress((void**)&X1,  g_X1);
    cudaGetSymbolAddress((void**)&X2,  g_X2);
    cudaGetSymbolAddress((void**)&S1,  g_S1);
    cudaGetSymbolAddress((void**)&S2P, g_S2P);
    cudaGetSymbolAddress((void**)&P,   g_P);

    const size_t gemm_smem = (size_t)GEMM_SMEM_FLOATS * sizeof(float);  // 55296 B
    cudaFuncSetAttribute(stage1_mma, cudaFuncAttributeMaxDynamicSharedMemorySize,
                         (int)gemm_smem);
    cudaFuncSetAttribute(stage2_mma, cudaFuncAttributeMaxDynamicSharedMemorySize,
                         (int)gemm_smem);

    // Stage 1: [X1|X2] = leaky(x @ [W1;W2]^T + bias)
    stage1_mma<<<dim3(MROWS / 32, 4), 256, gemm_smem>>>(x, W1, W2, b1, b2, X1, X2);

    // Stage 2: S1 = X1@Wp_a^T, S2P = X2@Wp_b^T + bp
    stage2_mma<<<dim3(MROWS / 32, 2, 2), 256, gemm_smem>>>(X1, X2, Wp, bp, S1, S2P);

    // Stage 3: pairwise sigmoid planes (register double-buffered kk loop)
    size_t pw_smem = (size_t)PW_U64_TOTAL * sizeof(u64);   // 68,104 B
    cudaFuncSetAttribute(pairwise_kernel,
                         cudaFuncAttributeMaxDynamicSharedMemorySize, (int)pw_smem);
    dim3 g3(N_NODES / 64, N_NODES / 64, BBATCH);   // 8 x 8 x 4 = 256
    pairwise_kernel<<<g3, dim3(256), pw_smem>>>(S1, S2P, Wb, bb, P);

    // Stage 4: epilogue (2 float4 per thread)
    finalize_kernel<<<N_NODES * N_NODES / 8 / 128, 128>>>(P, noise, out);
}